// round 15
// baseline (speedup 1.0000x reference)
#include <cuda_runtime.h>
#include <cuda_fp16.h>
#include <cstdint>

#define FEAT   128
#define HID    128
#define HID2   64
#define BM     128
#define THREADS 256
#define MAXN   10000
#define APITCH 136            // halves per row (272B) for the A tile

// smem layout (bytes)
#define SM_A    0                         // 128 x 136 fp16 = 34816
#define SM_BP   34816                     // fragment-ready B: 16384
#define SM_G1   51200
#define SM_BE1  51712
#define SM_B2   52224
#define SM_G2   52480
#define SM_BE2  52736
#define SM_W3   52992
#define SM_SRED 53248                     // float2 sred[128*2] = 2048
#define SM_DOT  55296                     // float dpart[128]   = 512
#define SM_TOTAL 55808                    // x4 CTAs = 223232 <= 228KB carveout

// fp16 per-node first-layer partials (drug table has b1 folded in)
__device__ __align__(16) __half   g_PdrugH[MAXN * HID];
__device__ __align__(16) __half   g_PdisH [MAXN * HID];
__device__ float g_Sdrug[MAXN];
__device__ float g_Sdis [MAXN];
// B fragments in HMMA order: [(nt*8+kt)*32 + lane] -> uint2 {b0, b1}
__device__ __align__(16) uint32_t g_W2p[8 * 8 * 32 * 2];

__device__ __forceinline__ float gelu_fast(float x) {
    const float x2 = x * x;
    const float inner = x * fmaf(0.0356774081f, x2, 0.7978845608f);
    float t;
    asm("tanh.approx.f32 %0, %1;" : "=f"(t) : "f"(inner));
    return 0.5f * x * (1.0f + t);
}

// ---------------------------------------------------------------------------
// Fused precompute: 64 nodes/block, per-node P tables (+b1 fold for drug),
// per-node sums, and (last block) the W2 fragment permute.
// ---------------------------------------------------------------------------
__global__ __launch_bounds__(THREADS) void precompute_kernel(
    const float* __restrict__ drug, const float* __restrict__ dis,
    const float* __restrict__ W1, const float* __restrict__ b1,
    const float* __restrict__ W2, int n_drug, int n_dis)
{
    if (blockIdx.x == gridDim.x - 1) {
        if (blockIdx.y == 0) {
            for (int i = threadIdx.x; i < 4096; i += THREADS) {
                const int w    = i & 1;
                const int lane = (i >> 1) & 31;
                const int kt   = (i >> 6) & 7;
                const int nt   = i >> 9;
                const int gid  = lane >> 2, tig = lane & 3;
                const int n    = nt * 8 + gid;
                const int kb   = kt * 16 + (w ? 8 : 0) + 2 * tig;
                const __half h0 = __float2half_rn(W2[kb * HID2 + n]);
                const __half h1 = __float2half_rn(W2[(kb + 1) * HID2 + n]);
                uint32_t word = ((uint32_t)*(const uint16_t*)&h1 << 16) | *(const uint16_t*)&h0;
                g_W2p[((nt * 8 + kt) * 32 + lane) * 2 + w] = word;
            }
        }
        return;
    }

    const int table = blockIdx.y;
    const int n = table ? n_dis : n_drug;
    const float* __restrict__ feat = table ? dis : drug;
    const float* __restrict__ w    = W1 + (table ? (size_t)FEAT * HID : 0);
    __half* __restrict__ outp      = table ? g_PdisH : g_PdrugH;
    float*  __restrict__ sump      = table ? g_Sdis  : g_Sdrug;

    const int n0 = blockIdx.x * 64;
    if (n0 >= n) return;

    __shared__ float fs[64][FEAT];     // 32 KB static
    const int tid = threadIdx.x;
    for (int idx = tid; idx < 64 * FEAT; idx += THREADS) {
        int node = idx >> 7, k = idx & 127;
        fs[node][k] = (n0 + node < n) ? feat[(size_t)(n0 + node) * FEAT + k] : 0.0f;
    }
    __syncthreads();

    const int tx = tid & 31, ty = tid >> 5;      // 8 node-groups of 8
    float acc[8][4] = {};
    #pragma unroll 2
    for (int k = 0; k < FEAT; ++k) {
        float wv[4];
        #pragma unroll
        for (int c = 0; c < 4; ++c) wv[c] = w[(size_t)k * HID + tx + 32 * c];
        #pragma unroll
        for (int i = 0; i < 8; ++i) {
            float f = fs[ty * 8 + i][k];
            #pragma unroll
            for (int c = 0; c < 4; ++c) acc[i][c] = fmaf(f, wv[c], acc[i][c]);
        }
    }
    if (table == 0) {
        #pragma unroll
        for (int i = 0; i < 8; ++i)
            #pragma unroll
            for (int c = 0; c < 4; ++c) acc[i][c] += b1[tx + 32 * c];
    }
    #pragma unroll
    for (int i = 0; i < 8; ++i) {
        const int node = n0 + ty * 8 + i;
        float loc = 0.0f;
        #pragma unroll
        for (int c = 0; c < 4; ++c) {
            const __half h = __float2half_rn(acc[i][c]);
            if (node < n) outp[(size_t)node * HID + tx + 32 * c] = h;
            loc += __half2float(h);
        }
        #pragma unroll
        for (int m = 16; m > 0; m >>= 1)
            loc += __shfl_xor_sync(0xffffffffu, loc, m);
        if (tx == 0 && node < n) sump[node] = loc;
    }
}

// ---------------------------------------------------------------------------
extern __shared__ char smem_raw[];

__global__ __launch_bounds__(THREADS, 4) void edge_kernel(
    const int* __restrict__ src, const int* __restrict__ dst,
    const float* __restrict__ g1, const float* __restrict__ be1,
    const float* __restrict__ b2, const float* __restrict__ g2, const float* __restrict__ be2,
    const float* __restrict__ W3, const float* __restrict__ b3,
    float* __restrict__ out, int E)
{
    __half* As   = (__half*)(smem_raw + SM_A);
    uint2*  Bp   = (uint2*)(smem_raw + SM_BP);
    float* g1s  = (float*)(smem_raw + SM_G1);
    float* be1s = (float*)(smem_raw + SM_BE1);
    float* b2s  = (float*)(smem_raw + SM_B2);
    float* g2s  = (float*)(smem_raw + SM_G2);
    float* be2s = (float*)(smem_raw + SM_BE2);
    float* w3s  = (float*)(smem_raw + SM_W3);
    float2* sred = (float2*)(smem_raw + SM_SRED);
    float*  dpart = (float*)(smem_raw + SM_DOT);

    const int tid = threadIdx.x;
    const int wid = tid >> 5, lane = tid & 31;
    const int e0 = blockIdx.x * BM;
    const int r0 = wid * 16;                 // phase-1 rows for this warp
    const int rg = wid >> 1, cg = wid & 1;   // phase-2/3 tile
    const int rbase = rg * 32;
    const int barid = 1 + rg;

    // Batched index load FIRST; latency hidden behind smem fill + barrier.
    int eidx = e0 + r0 + (lane & 15);
    if (eidx >= E) eidx = E - 1;
    const int idx32 = (lane < 16) ? src[eidx] : dst[eidx];

    if (tid < HID)  { g1s[tid] = g1[tid]; be1s[tid] = be1[tid]; }
    if (tid < HID2) { b2s[tid] = b2[tid]; g2s[tid] = g2[tid]; be2s[tid] = be2[tid]; w3s[tid] = W3[tid]; }

    {
        const uint4* __restrict__ w2v = (const uint4*)g_W2p;
        #pragma unroll
        for (int i = tid; i < 1024; i += THREADS)
            ((uint4*)Bp)[i] = w2v[i];
    }
    __syncthreads();

    // ---------------- Phase 1: rows r0..r0+15, prefetch + analytic mean ----
    {
        const float4 gg = reinterpret_cast<const float4*>(g1s)[lane];
        const float4 ee = reinterpret_cast<const float4*>(be1s)[lane];

        uint2 ap[2][4], qp[2][4];
        float sv[2][4];
        #pragma unroll
        for (int r = 0; r < 4; ++r) {
            const int s = __shfl_sync(0xffffffffu, idx32, r);
            const int d = __shfl_sync(0xffffffffu, idx32, 16 + r);
            ap[0][r] = *(const uint2*)(g_PdrugH + (size_t)s * HID + lane * 4);
            qp[0][r] = *(const uint2*)(g_PdisH  + (size_t)d * HID + lane * 4);
            sv[0][r] = g_Sdrug[s] + g_Sdis[d];
        }

        #pragma unroll
        for (int ib = 0; ib < 4; ++ib) {
            const int cur = ib & 1, nxt = cur ^ 1;
            if (ib < 3) {
                #pragma unroll
                for (int r = 0; r < 4; ++r) {
                    const int s = __shfl_sync(0xffffffffu, idx32, (ib + 1) * 4 + r);
                    const int d = __shfl_sync(0xffffffffu, idx32, 16 + (ib + 1) * 4 + r);
                    ap[nxt][r] = *(const uint2*)(g_PdrugH + (size_t)s * HID + lane * 4);
                    qp[nxt][r] = *(const uint2*)(g_PdisH  + (size_t)d * HID + lane * 4);
                    sv[nxt][r] = g_Sdrug[s] + g_Sdis[d];
                }
            }
            #pragma unroll
            for (int r = 0; r < 4; ++r) {
                const float2 a01 = __half22float2(*(const __half2*)&ap[cur][r].x);
                const float2 a23 = __half22float2(*(const __half2*)&ap[cur][r].y);
                const float2 q01 = __half22float2(*(const __half2*)&qp[cur][r].x);
                const float2 q23 = __half22float2(*(const __half2*)&qp[cur][r].y);
                float v[4];
                v[0] = a01.x + q01.x;
                v[1] = a01.y + q01.y;
                v[2] = a23.x + q23.x;
                v[3] = a23.y + q23.y;
                const float mu = sv[cur][r] * (1.0f / HID);
                float s2r = v[0]*v[0] + v[1]*v[1] + v[2]*v[2] + v[3]*v[3];
                #pragma unroll
                for (int m = 16; m > 0; m >>= 1)
                    s2r += __shfl_xor_sync(0xffffffffu, s2r, m);
                const float var = s2r * (1.0f / HID) - mu * mu;
                const float rs  = rsqrtf(var + 1e-5f);
                float h0 = gelu_fast((v[0] - mu) * rs * gg.x + ee.x);
                float h1 = gelu_fast((v[1] - mu) * rs * gg.y + ee.y);
                float h2 = gelu_fast((v[2] - mu) * rs * gg.z + ee.z);
                float h3 = gelu_fast((v[3] - mu) * rs * gg.w + ee.w);
                __half2 p0 = __floats2half2_rn(h0, h1);
                __half2 p1 = __floats2half2_rn(h2, h3);
                uint2 pk;
                pk.x = *reinterpret_cast<uint32_t*>(&p0);
                pk.y = *reinterpret_cast<uint32_t*>(&p1);
                *(uint2*)(As + (r0 + ib * 4 + r) * APITCH + lane * 4) = pk;
            }
        }
    }
    // pair barrier: warps 2rg, 2rg+1 produced rows rbase..rbase+31
    asm volatile("bar.sync %0, 64;" :: "r"(barid) : "memory");

    // ---------------- Phase 2: 32 rows x 32 cols per warp -------------------
    const int gid = lane >> 2, tig = lane & 3;

    float acc[2][4][4];   // [mtile][ntile j][frag]
    #pragma unroll
    for (int mt = 0; mt < 2; ++mt)
        #pragma unroll
        for (int j = 0; j < 4; ++j)
            #pragma unroll
            for (int f = 0; f < 4; ++f) acc[mt][j][f] = 0.0f;

    #pragma unroll
    for (int kt = 0; kt < 8; ++kt) {
        const int k0 = kt * 16;
        const uint32_t* ar0 = (const uint32_t*)(As + (rbase + gid)      * APITCH + k0);
        const uint32_t* ar1 = (const uint32_t*)(As + (rbase + gid + 8)  * APITCH + k0);
        const uint32_t* ar2 = (const uint32_t*)(As + (rbase + gid + 16) * APITCH + k0);
        const uint32_t* ar3 = (const uint32_t*)(As + (rbase + gid + 24) * APITCH + k0);
        uint32_t a00 = ar0[tig], a01 = ar1[tig], a02 = ar0[tig + 4], a03 = ar1[tig + 4];
        uint32_t a10 = ar2[tig], a11 = ar3[tig], a12 = ar2[tig + 4], a13 = ar3[tig + 4];
        #pragma unroll
        for (int j = 0; j < 4; ++j) {
            const uint2 bw = Bp[((cg * 4 + j) * 8 + kt) * 32 + lane];
            asm volatile(
                "mma.sync.aligned.m16n8k16.row.col.f32.f16.f16.f32 "
                "{%0,%1,%2,%3}, {%4,%5,%6,%7}, {%8,%9}, {%0,%1,%2,%3};"
                : "+f"(acc[0][j][0]), "+f"(acc[0][j][1]), "+f"(acc[0][j][2]), "+f"(acc[0][j][3])
                : "r"(a00), "r"(a01), "r"(a02), "r"(a03), "r"(bw.x), "r"(bw.y));
            asm volatile(
                "mma.sync.aligned.m16n8k16.row.col.f32.f16.f16.f32 "
                "{%0,%1,%2,%3}, {%4,%5,%6,%7}, {%8,%9}, {%0,%1,%2,%3};"
                : "+f"(acc[1][j][0]), "+f"(acc[1][j][1]), "+f"(acc[1][j][2]), "+f"(acc[1][j][3])
                : "r"(a10), "r"(a11), "r"(a12), "r"(a13), "r"(bw.x), "r"(bw.y));
        }
    }

    // ---------------- Phase 3: cross-warp LN(64) ; GELU ; dot(W3)+b3 -------
    // lane rows: slot = mt*2+rr -> row = rbase + mt*16 + rr*8 + gid
    float s1v[4], s2v[4];
    #pragma unroll
    for (int mt = 0; mt < 2; ++mt) {
        #pragma unroll
        for (int rr = 0; rr < 2; ++rr) {
            float s1 = 0.f, s2 = 0.f;
            #pragma unroll
            for (int j = 0; j < 4; ++j) {
                #pragma unroll
                for (int jj = 0; jj < 2; ++jj) {
                    const int col = (cg * 4 + j) * 8 + 2 * tig + jj;
                    float val = acc[mt][j][rr * 2 + jj] + b2s[col];
                    acc[mt][j][rr * 2 + jj] = val;
                    s1 += val; s2 += val * val;
                }
            }
            s1v[mt * 2 + rr] = s1; s2v[mt * 2 + rr] = s2;
        }
    }
    #pragma unroll
    for (int m = 1; m <= 2; m <<= 1) {
        #pragma unroll
        for (int sl = 0; sl < 4; ++sl) {
            s1v[sl] += __shfl_xor_sync(0xffffffffu, s1v[sl], m);
            s2v[sl] += __shfl_xor_sync(0xffffffffu, s2v[sl], m);
        }
    }
    if (tig == 0) {
        #pragma unroll
        for (int sl = 0; sl < 4; ++sl) {
            const int row = rbase + (sl >> 1) * 16 + (sl & 1) * 8 + gid;
            sred[row * 2 + cg] = make_float2(s1v[sl], s2v[sl]);
        }
    }
    asm volatile("bar.sync %0, 64;" :: "r"(barid) : "memory");

    float mur[4], rsr[4];
    #pragma unroll
    for (int sl = 0; sl < 4; ++sl) {
        const int row = rbase + (sl >> 1) * 16 + (sl & 1) * 8 + gid;
        const float2 o = sred[row * 2 + (cg ^ 1)];
        const float t1 = s1v[sl] + o.x, t2 = s2v[sl] + o.y;
        const float mu = t1 * (1.0f / HID2);
        mur[sl] = mu;
        rsr[sl] = rsqrtf(t2 * (1.0f / HID2) - mu * mu + 1e-5f);
    }

    float dotv[4] = {0.f, 0.f, 0.f, 0.f};
    #pragma unroll
    for (int mt = 0; mt < 2; ++mt) {
        #pragma unroll
        for (int rr = 0; rr < 2; ++rr) {
            const int sl = mt * 2 + rr;
            #pragma unroll
            for (int j = 0; j < 4; ++j) {
                #pragma unroll
                for (int jj = 0; jj < 2; ++jj) {
                    const int col = (cg * 4 + j) * 8 + 2 * tig + jj;
                    const float zz = (acc[mt][j][rr * 2 + jj] - mur[sl]) * rsr[sl] * g2s[col] + be2s[col];
                    dotv[sl] = fmaf(gelu_fast(zz), w3s[col], dotv[sl]);
                }
            }
        }
    }
    #pragma unroll
    for (int m = 1; m <= 2; m <<= 1)
        #pragma unroll
        for (int sl = 0; sl < 4; ++sl)
            dotv[sl] += __shfl_xor_sync(0xffffffffu, dotv[sl], m);

    if (cg == 1 && tig == 0) {
        #pragma unroll
        for (int sl = 0; sl < 4; ++sl) {
            const int row = rbase + (sl >> 1) * 16 + (sl & 1) * 8 + gid;
            dpart[row] = dotv[sl];
        }
    }
    asm volatile("bar.sync %0, 64;" :: "r"(barid) : "memory");

    if (cg == 0 && tig == 0) {
        const float b3v = b3[0];
        #pragma unroll
        for (int sl = 0; sl < 4; ++sl) {
            const int row = rbase + (sl >> 1) * 16 + (sl & 1) * 8 + gid;
            const int e = e0 + row;
            if (e < E) out[e] = dotv[sl] + dpart[row] + b3v;
        }
    }
}

// ---------------------------------------------------------------------------
extern "C" void kernel_launch(void* const* d_in, const int* in_sizes, int n_in,
                              void* d_out, int out_size)
{
    const float* drug = (const float*)d_in[0];
    const float* dis  = (const float*)d_in[1];
    const int*   src  = (const int*)  d_in[2];
    const int*   dst  = (const int*)  d_in[3];
    const float* W1   = (const float*)d_in[4];
    const float* b1   = (const float*)d_in[5];
    const float* g1   = (const float*)d_in[6];
    const float* be1  = (const float*)d_in[7];
    const float* W2   = (const float*)d_in[8];
    const float* b2   = (const float*)d_in[9];
    const float* g2   = (const float*)d_in[10];
    const float* be2  = (const float*)d_in[11];
    const float* W3   = (const float*)d_in[12];
    const float* b3   = (const float*)d_in[13];
    float* out = (float*)d_out;

    const int n_drug = in_sizes[0] / FEAT;
    const int n_dis  = in_sizes[1] / FEAT;
    const int E      = in_sizes[2];

    const int nmax = n_drug > n_dis ? n_drug : n_dis;
    dim3 pgrid((nmax + 63) / 64 + 1, 2);    // +1 block row for the W2 permute
    precompute_kernel<<<pgrid, THREADS>>>(drug, dis, W1, b1, W2, n_drug, n_dis);

    cudaFuncSetAttribute(edge_kernel, cudaFuncAttributeMaxDynamicSharedMemorySize, SM_TOTAL);
    const int blocks = (E + BM - 1) / BM;
    edge_kernel<<<blocks, THREADS, SM_TOTAL>>>(
        src, dst, g1, be1, b2, g2, be2, W3, b3, out, E);
}

// round 16
// speedup vs baseline: 1.0889x; 1.0889x over previous
#include <cuda_runtime.h>
#include <cuda_fp16.h>
#include <cstdint>

#define FEAT   128
#define HID    128
#define HID2   64
#define BM     128
#define THREADS 256
#define MAXN   10000
#define APITCH 136            // halves per row (272B) for the A tile

// smem layout (bytes)
#define SM_A    0                         // 128 x 136 fp16 = 34816
#define SM_BP   (128 * APITCH * 2)        // fragment-ready B: 16384
#define SM_G1   (SM_BP + 16384)
#define SM_BE1  (SM_G1 + 512)
#define SM_B2   (SM_BE1 + 512)
#define SM_G2   (SM_B2 + 256)
#define SM_BE2  (SM_G2 + 256)
#define SM_W3   (SM_BE2 + 256)
#define SM_TOTAL (SM_W3 + 256)            // 53248 B

// fp16 per-node first-layer partials (drug table has b1 folded in)
__device__ __align__(16) __half   g_PdrugH[MAXN * HID];
__device__ __align__(16) __half   g_PdisH [MAXN * HID];
// per-node sums of the fp16 table rows (for analytic LN mean)
__device__ float g_Sdrug[MAXN];
__device__ float g_Sdis [MAXN];
// B fragments in HMMA order: [(nt*8+kt)*32 + lane] -> uint2 {b0, b1}
__device__ __align__(16) uint32_t g_W2p[8 * 8 * 32 * 2];

// tanh-GELU, re-associated: 5 fma-pipe ops + 1 MUFU
__device__ __forceinline__ float gelu_fast(float x) {
    const float hx = 0.5f * x;
    const float x2 = x * x;
    const float inner = x * fmaf(0.0356774081f, x2, 0.7978845608f);
    float t;
    asm("tanh.approx.f32 %0, %1;" : "=f"(t) : "f"(inner));
    return fmaf(hx, t, hx);
}

// ---------------------------------------------------------------------------
// Fused precompute: per-node P tables (+b1 fold for drug), per-node sums,
// and (last block) the W2 fragment permute.
// ---------------------------------------------------------------------------
__global__ __launch_bounds__(THREADS) void precompute_kernel(
    const float* __restrict__ drug, const float* __restrict__ dis,
    const float* __restrict__ W1, const float* __restrict__ b1,
    const float* __restrict__ W2, int n_drug, int n_dis)
{
    // Last block row 0: W2 -> fragment-ready fp16 permute
    if (blockIdx.x == gridDim.x - 1) {
        if (blockIdx.y == 0) {
            for (int i = threadIdx.x; i < 4096; i += THREADS) {
                const int w    = i & 1;
                const int lane = (i >> 1) & 31;
                const int kt   = (i >> 6) & 7;
                const int nt   = i >> 9;
                const int gid  = lane >> 2, tig = lane & 3;
                const int n    = nt * 8 + gid;
                const int kb   = kt * 16 + (w ? 8 : 0) + 2 * tig;
                const __half h0 = __float2half_rn(W2[kb * HID2 + n]);
                const __half h1 = __float2half_rn(W2[(kb + 1) * HID2 + n]);
                uint32_t word = ((uint32_t)*(const uint16_t*)&h1 << 16) | *(const uint16_t*)&h0;
                g_W2p[((nt * 8 + kt) * 32 + lane) * 2 + w] = word;
            }
        }
        return;
    }

    const int table = blockIdx.y;
    const int n = table ? n_dis : n_drug;
    const float* __restrict__ feat = table ? dis : drug;
    const float* __restrict__ w    = W1 + (table ? (size_t)FEAT * HID : 0);
    __half* __restrict__ outp      = table ? g_PdisH : g_PdrugH;
    float*  __restrict__ sump      = table ? g_Sdis  : g_Sdrug;

    const int n0 = blockIdx.x * 32;
    if (n0 >= n) return;

    __shared__ float fs[32][FEAT];
    const int tid = threadIdx.x;
    for (int idx = tid; idx < 32 * FEAT; idx += THREADS) {
        int node = idx >> 7, k = idx & 127;
        fs[node][k] = (n0 + node < n) ? feat[(size_t)(n0 + node) * FEAT + k] : 0.0f;
    }
    __syncthreads();

    const int tx = tid & 31, ty = tid >> 5;
    float acc[4][4] = {};
    #pragma unroll 4
    for (int k = 0; k < FEAT; ++k) {
        float wv[4];
        #pragma unroll
        for (int c = 0; c < 4; ++c) wv[c] = w[(size_t)k * HID + tx + 32 * c];
        #pragma unroll
        for (int i = 0; i < 4; ++i) {
            float f = fs[ty * 4 + i][k];
            #pragma unroll
            for (int c = 0; c < 4; ++c) acc[i][c] = fmaf(f, wv[c], acc[i][c]);
        }
    }
    // fold b1 into the drug table
    if (table == 0) {
        #pragma unroll
        for (int i = 0; i < 4; ++i)
            #pragma unroll
            for (int c = 0; c < 4; ++c) acc[i][c] += b1[tx + 32 * c];
    }
    #pragma unroll
    for (int i = 0; i < 4; ++i) {
        const int node = n0 + ty * 4 + i;
        float loc = 0.0f;
        #pragma unroll
        for (int c = 0; c < 4; ++c) {
            const __half h = __float2half_rn(acc[i][c]);
            if (node < n) outp[(size_t)node * HID + tx + 32 * c] = h;
            loc += __half2float(h);
        }
        #pragma unroll
        for (int m = 16; m > 0; m >>= 1)
            loc += __shfl_xor_sync(0xffffffffu, loc, m);
        if (tx == 0 && node < n) sump[node] = loc;
    }
}

// ---------------------------------------------------------------------------
extern __shared__ char smem_raw[];

__global__ __launch_bounds__(THREADS, 4) void edge_kernel(
    const int* __restrict__ src, const int* __restrict__ dst,
    const float* __restrict__ g1, const float* __restrict__ be1,
    const float* __restrict__ b2, const float* __restrict__ g2, const float* __restrict__ be2,
    const float* __restrict__ W3, const float* __restrict__ b3,
    float* __restrict__ out, int E)
{
    __half* As   = (__half*)(smem_raw + SM_A);
    uint2*  Bp   = (uint2*)(smem_raw + SM_BP);
    float* g1s  = (float*)(smem_raw + SM_G1);
    float* be1s = (float*)(smem_raw + SM_BE1);
    float* b2s  = (float*)(smem_raw + SM_B2);
    float* g2s  = (float*)(smem_raw + SM_G2);
    float* be2s = (float*)(smem_raw + SM_BE2);
    float* w3s  = (float*)(smem_raw + SM_W3);

    const int tid = threadIdx.x;
    const int wid = tid >> 5, lane = tid & 31;
    const int e0 = blockIdx.x * BM;
    const int r0 = wid * 16;

    // Batched index load FIRST; latency hidden behind smem fill + barrier.
    int eidx = e0 + r0 + (lane & 15);
    if (eidx >= E) eidx = E - 1;                 // clamp (finite garbage ok)
    const int idx32 = (lane < 16) ? src[eidx] : dst[eidx];

    if (tid < HID)  { g1s[tid] = g1[tid]; be1s[tid] = be1[tid]; }
    if (tid < HID2) { b2s[tid] = b2[tid]; g2s[tid] = g2[tid]; be2s[tid] = be2[tid]; w3s[tid] = W3[tid]; }

    // copy fragment-ready B (16 KB) with uint4 vectors
    {
        const uint4* __restrict__ w2v = (const uint4*)g_W2p;   // 1024 uint4
        #pragma unroll
        for (int i = tid; i < 1024; i += THREADS)
            ((uint4*)Bp)[i] = w2v[i];
    }
    __syncthreads();

    // ---------------- Phase 1: warp-local rows, prefetch + analytic mean ---
    {
        const float4 gg = reinterpret_cast<const float4*>(g1s)[lane];
        const float4 ee = reinterpret_cast<const float4*>(be1s)[lane];

        uint2 ap[2][4], qp[2][4];
        float sv[2][4];
        // prologue: batch 0
        #pragma unroll
        for (int r = 0; r < 4; ++r) {
            const int s = __shfl_sync(0xffffffffu, idx32, r);
            const int d = __shfl_sync(0xffffffffu, idx32, 16 + r);
            ap[0][r] = *(const uint2*)(g_PdrugH + (size_t)s * HID + lane * 4);
            qp[0][r] = *(const uint2*)(g_PdisH  + (size_t)d * HID + lane * 4);
            sv[0][r] = g_Sdrug[s] + g_Sdis[d];
        }

        #pragma unroll
        for (int ib = 0; ib < 4; ++ib) {
            const int cur = ib & 1, nxt = cur ^ 1;
            if (ib < 3) {
                #pragma unroll
                for (int r = 0; r < 4; ++r) {
                    const int s = __shfl_sync(0xffffffffu, idx32, (ib + 1) * 4 + r);
                    const int d = __shfl_sync(0xffffffffu, idx32, 16 + (ib + 1) * 4 + r);
                    ap[nxt][r] = *(const uint2*)(g_PdrugH + (size_t)s * HID + lane * 4);
                    qp[nxt][r] = *(const uint2*)(g_PdisH  + (size_t)d * HID + lane * 4);
                    sv[nxt][r] = g_Sdrug[s] + g_Sdis[d];
                }
            }
            #pragma unroll
            for (int r = 0; r < 4; ++r) {
                const float2 a01 = __half22float2(*(const __half2*)&ap[cur][r].x);
                const float2 a23 = __half22float2(*(const __half2*)&ap[cur][r].y);
                const float2 q01 = __half22float2(*(const __half2*)&qp[cur][r].x);
                const float2 q23 = __half22float2(*(const __half2*)&qp[cur][r].y);
                float v[4];
                v[0] = a01.x + q01.x;
                v[1] = a01.y + q01.y;
                v[2] = a23.x + q23.x;
                v[3] = a23.y + q23.y;
                // mean from precomputed node sums (no shuffle)
                const float mu = sv[cur][r] * (1.0f / HID);
                float s2r = v[0]*v[0] + v[1]*v[1] + v[2]*v[2] + v[3]*v[3];
                #pragma unroll
                for (int m = 16; m > 0; m >>= 1)
                    s2r += __shfl_xor_sync(0xffffffffu, s2r, m);
                const float var = s2r * (1.0f / HID) - mu * mu;
                const float rs  = rsqrtf(var + 1e-5f);
                float h0 = gelu_fast((v[0] - mu) * rs * gg.x + ee.x);
                float h1 = gelu_fast((v[1] - mu) * rs * gg.y + ee.y);
                float h2 = gelu_fast((v[2] - mu) * rs * gg.z + ee.z);
                float h3 = gelu_fast((v[3] - mu) * rs * gg.w + ee.w);
                __half2 p0 = __floats2half2_rn(h0, h1);
                __half2 p1 = __floats2half2_rn(h2, h3);
                uint2 pk;
                pk.x = *reinterpret_cast<uint32_t*>(&p0);
                pk.y = *reinterpret_cast<uint32_t*>(&p1);
                *(uint2*)(As + (r0 + ib * 4 + r) * APITCH + lane * 4) = pk;
            }
        }
    }
    __syncwarp();   // A rows are warp-private

    // ---------------- Phase 2: HMMA m16n8k16; A scalar LDS, B LDS.64 -------
    const int gid = lane >> 2, tig = lane & 3;

    float acc[8][4];
    #pragma unroll
    for (int nt = 0; nt < 8; ++nt)
        #pragma unroll
        for (int j = 0; j < 4; ++j) acc[nt][j] = 0.0f;

    #pragma unroll
    for (int kt = 0; kt < 8; ++kt) {
        const int k0 = kt * 16;
        const uint32_t* arow0 = (const uint32_t*)(As + (r0 + gid) * APITCH + k0);
        const uint32_t* arow8 = (const uint32_t*)(As + (r0 + gid + 8) * APITCH + k0);
        uint32_t a0 = arow0[tig];
        uint32_t a1 = arow8[tig];
        uint32_t a2 = arow0[tig + 4];
        uint32_t a3 = arow8[tig + 4];
        #pragma unroll
        for (int nt = 0; nt < 8; ++nt) {
            const uint2 bw = Bp[(nt * 8 + kt) * 32 + lane];
            asm volatile(
                "mma.sync.aligned.m16n8k16.row.col.f32.f16.f16.f32 "
                "{%0,%1,%2,%3}, {%4,%5,%6,%7}, {%8,%9}, {%0,%1,%2,%3};"
                : "+f"(acc[nt][0]), "+f"(acc[nt][1]), "+f"(acc[nt][2]), "+f"(acc[nt][3])
                : "r"(a0), "r"(a1), "r"(a2), "r"(a3), "r"(bw.x), "r"(bw.y));
        }
    }

    // ---------------- Phase 3: +b2 (in acc) ; LN(64) ; GELU ; dot(W3)+b3 ---
    float s1a = 0.f, s2a = 0.f, s1b = 0.f, s2b = 0.f;
    #pragma unroll
    for (int nt = 0; nt < 8; ++nt) {
        #pragma unroll
        for (int j = 0; j < 2; ++j) {
            const float bb = b2s[nt * 8 + 2 * tig + j];
            acc[nt][j]     += bb;
            acc[nt][2 + j] += bb;
            const float tA = acc[nt][j];
            const float tB = acc[nt][2 + j];
            s1a += tA; s2a += tA * tA;
            s1b += tB; s2b += tB * tB;
        }
    }
    #pragma unroll
    for (int m = 1; m <= 2; m <<= 1) {
        s1a += __shfl_xor_sync(0xffffffffu, s1a, m);
        s2a += __shfl_xor_sync(0xffffffffu, s2a, m);
        s1b += __shfl_xor_sync(0xffffffffu, s1b, m);
        s2b += __shfl_xor_sync(0xffffffffu, s2b, m);
    }
    const float muA = s1a * (1.0f / HID2);
    const float rsA = rsqrtf(s2a * (1.0f / HID2) - muA * muA + 1e-5f);
    const float muB = s1b * (1.0f / HID2);
    const float rsB = rsqrtf(s2b * (1.0f / HID2) - muB * muB + 1e-5f);

    float dotA = 0.f, dotB = 0.f;
    #pragma unroll
    for (int nt = 0; nt < 8; ++nt) {
        #pragma unroll
        for (int j = 0; j < 2; ++j) {
            const int col = nt * 8 + 2 * tig + j;
            const float gg = g2s[col], be = be2s[col], ww = w3s[col];
            dotA = fmaf(gelu_fast((acc[nt][j]     - muA) * rsA * gg + be), ww, dotA);
            dotB = fmaf(gelu_fast((acc[nt][2 + j] - muB) * rsB * gg + be), ww, dotB);
        }
    }
    #pragma unroll
    for (int m = 1; m <= 2; m <<= 1) {
        dotA += __shfl_xor_sync(0xffffffffu, dotA, m);
        dotB += __shfl_xor_sync(0xffffffffu, dotB, m);
    }

    if (tig == 0) {
        const float b3v = b3[0];
        const int eA = e0 + r0 + gid;
        const int eB = eA + 8;
        if (eA < E) out[eA] = dotA + b3v;
        if (eB < E) out[eB] = dotB + b3v;
    }
}

// ---------------------------------------------------------------------------
extern "C" void kernel_launch(void* const* d_in, const int* in_sizes, int n_in,
                              void* d_out, int out_size)
{
    const float* drug = (const float*)d_in[0];
    const float* dis  = (const float*)d_in[1];
    const int*   src  = (const int*)  d_in[2];
    const int*   dst  = (const int*)  d_in[3];
    const float* W1   = (const float*)d_in[4];
    const float* b1   = (const float*)d_in[5];
    const float* g1   = (const float*)d_in[6];
    const float* be1  = (const float*)d_in[7];
    const float* W2   = (const float*)d_in[8];
    const float* b2   = (const float*)d_in[9];
    const float* g2   = (const float*)d_in[10];
    const float* be2  = (const float*)d_in[11];
    const float* W3   = (const float*)d_in[12];
    const float* b3   = (const float*)d_in[13];
    float* out = (float*)d_out;

    const int n_drug = in_sizes[0] / FEAT;
    const int n_dis  = in_sizes[1] / FEAT;
    const int E      = in_sizes[2];

    const int nmax = n_drug > n_dis ? n_drug : n_dis;
    dim3 pgrid((nmax + 31) / 32 + 1, 2);    // +1 block row for the W2 permute
    precompute_kernel<<<pgrid, THREADS>>>(drug, dis, W1, b1, W2, n_drug, n_dis);

    cudaFuncSetAttribute(edge_kernel, cudaFuncAttributeMaxDynamicSharedMemorySize, SM_TOTAL);
    const int blocks = (E + BM - 1) / BM;
    edge_kernel<<<blocks, THREADS, SM_TOTAL>>>(
        src, dst, g1, be1, b2, g2, be2, W3, b3, out, E);
}

// round 17
// speedup vs baseline: 1.1264x; 1.0344x over previous
#include <cuda_runtime.h>
#include <cuda_fp16.h>
#include <cstdint>

#define FEAT   128
#define HID    128
#define HID2   64
#define BM     128
#define THREADS 256
#define MAXN   10000
#define APITCH 136            // halves per row (272B) for the A tile

// smem layout (bytes)
#define SM_A    0                         // 128 x 136 fp16 = 34816
#define SM_BP   (128 * APITCH * 2)        // fragment-ready B: 16384
#define SM_G1H  (SM_BP + 16384)           // g1 as half2: 256 B
#define SM_BE1H (SM_G1H + 256)            // be1 as half2: 256 B
#define SM_B2   (SM_BE1H + 256)
#define SM_G2   (SM_B2 + 256)
#define SM_BE2  (SM_G2 + 256)
#define SM_W3   (SM_BE2 + 256)
#define SM_TOTAL (SM_W3 + 256)            // 52736 B

// fp16 per-node first-layer partials (drug table has b1 folded in)
__device__ __align__(16) __half   g_PdrugH[MAXN * HID];
__device__ __align__(16) __half   g_PdisH [MAXN * HID];
__device__ float g_Sdrug[MAXN];
__device__ float g_Sdis [MAXN];
// B fragments in HMMA order: [(nt*8+kt)*32 + lane] -> uint2 {b0, b1}
__device__ __align__(16) uint32_t g_W2p[8 * 8 * 32 * 2];

// scalar tanh-GELU (fp32): 5 fma-pipe ops + 1 MUFU
__device__ __forceinline__ float gelu_fast(float x) {
    const float hx = 0.5f * x;
    const float x2 = x * x;
    const float inner = x * fmaf(0.0356774081f, x2, 0.7978845608f);
    float t;
    asm("tanh.approx.f32 %0, %1;" : "=f"(t) : "f"(inner));
    return fmaf(hx, t, hx);
}

// packed fp16x2 tanh-GELU: ~4 HFMA2 + 1 MUFU for TWO values
__device__ __forceinline__ __half2 gelu2h(__half2 x) {
    const __half2 c0 = __float2half2_rn(0.0356774081f);
    const __half2 c1 = __float2half2_rn(0.7978845608f);
    const __half2 ch = __float2half2_rn(0.5f);
    __half2 inner = __hmul2(x, __hfma2(c0, __hmul2(x, x), c1));
    uint32_t ti;
    asm("tanh.approx.f16x2 %0, %1;" : "=r"(ti) : "r"(*(uint32_t*)&inner));
    __half2 t = *(__half2*)&ti;
    __half2 hx = __hmul2(ch, x);
    return __hfma2(hx, t, hx);
}

// ---------------------------------------------------------------------------
// Fused precompute: per-node P tables (+b1 fold for drug), per-node sums,
// and (last block) the W2 fragment permute. W1 read via float4 (vectorized).
// Thread handles 4 CONSECUTIVE output columns (tx*4 .. tx*4+3).
// ---------------------------------------------------------------------------
__global__ __launch_bounds__(THREADS) void precompute_kernel(
    const float* __restrict__ drug, const float* __restrict__ dis,
    const float* __restrict__ W1, const float* __restrict__ b1,
    const float* __restrict__ W2, int n_drug, int n_dis)
{
    if (blockIdx.x == gridDim.x - 1) {
        if (blockIdx.y == 0) {
            for (int i = threadIdx.x; i < 4096; i += THREADS) {
                const int w    = i & 1;
                const int lane = (i >> 1) & 31;
                const int kt   = (i >> 6) & 7;
                const int nt   = i >> 9;
                const int gid  = lane >> 2, tig = lane & 3;
                const int n    = nt * 8 + gid;
                const int kb   = kt * 16 + (w ? 8 : 0) + 2 * tig;
                const __half h0 = __float2half_rn(W2[kb * HID2 + n]);
                const __half h1 = __float2half_rn(W2[(kb + 1) * HID2 + n]);
                uint32_t word = ((uint32_t)*(const uint16_t*)&h1 << 16) | *(const uint16_t*)&h0;
                g_W2p[((nt * 8 + kt) * 32 + lane) * 2 + w] = word;
            }
        }
        return;
    }

    const int table = blockIdx.y;
    const int n = table ? n_dis : n_drug;
    const float* __restrict__ feat = table ? dis : drug;
    const float* __restrict__ w    = W1 + (table ? (size_t)FEAT * HID : 0);
    __half* __restrict__ outp      = table ? g_PdisH : g_PdrugH;
    float*  __restrict__ sump      = table ? g_Sdis  : g_Sdrug;

    const int n0 = blockIdx.x * 32;
    if (n0 >= n) return;

    __shared__ float fs[32][FEAT];
    const int tid = threadIdx.x;
    for (int idx = tid; idx < 32 * FEAT; idx += THREADS) {
        int node = idx >> 7, k = idx & 127;
        fs[node][k] = (n0 + node < n) ? feat[(size_t)(n0 + node) * FEAT + k] : 0.0f;
    }
    __syncthreads();

    const int tx = tid & 31, ty = tid >> 5;
    float acc[4][4] = {};
    #pragma unroll 4
    for (int k = 0; k < FEAT; ++k) {
        const float4 wv = *reinterpret_cast<const float4*>(&w[(size_t)k * HID + tx * 4]);
        #pragma unroll
        for (int i = 0; i < 4; ++i) {
            const float f = fs[ty * 4 + i][k];
            acc[i][0] = fmaf(f, wv.x, acc[i][0]);
            acc[i][1] = fmaf(f, wv.y, acc[i][1]);
            acc[i][2] = fmaf(f, wv.z, acc[i][2]);
            acc[i][3] = fmaf(f, wv.w, acc[i][3]);
        }
    }
    if (table == 0) {
        const float4 bv = *reinterpret_cast<const float4*>(&b1[tx * 4]);
        #pragma unroll
        for (int i = 0; i < 4; ++i) {
            acc[i][0] += bv.x; acc[i][1] += bv.y;
            acc[i][2] += bv.z; acc[i][3] += bv.w;
        }
    }
    #pragma unroll
    for (int i = 0; i < 4; ++i) {
        const int node = n0 + ty * 4 + i;
        const __half2 p0 = __floats2half2_rn(acc[i][0], acc[i][1]);
        const __half2 p1 = __floats2half2_rn(acc[i][2], acc[i][3]);
        if (node < n) {
            uint2 pk;
            pk.x = *(const uint32_t*)&p0;
            pk.y = *(const uint32_t*)&p1;
            *reinterpret_cast<uint2*>(outp + (size_t)node * HID + tx * 4) = pk;
        }
        const float2 f0 = __half22float2(p0);
        const float2 f1 = __half22float2(p1);
        float loc = (f0.x + f0.y) + (f1.x + f1.y);
        #pragma unroll
        for (int m = 16; m > 0; m >>= 1)
            loc += __shfl_xor_sync(0xffffffffu, loc, m);
        if (tx == 0 && node < n) sump[node] = loc;
    }
}

// ---------------------------------------------------------------------------
extern __shared__ char smem_raw[];

__global__ __launch_bounds__(THREADS, 4) void edge_kernel(
    const int* __restrict__ src, const int* __restrict__ dst,
    const float* __restrict__ g1, const float* __restrict__ be1,
    const float* __restrict__ b2, const float* __restrict__ g2, const float* __restrict__ be2,
    const float* __restrict__ W3, const float* __restrict__ b3,
    float* __restrict__ out, int E)
{
    __half* As    = (__half*)(smem_raw + SM_A);
    uint2*  Bp    = (uint2*)(smem_raw + SM_BP);
    __half2* g1h  = (__half2*)(smem_raw + SM_G1H);
    __half2* be1h = (__half2*)(smem_raw + SM_BE1H);
    float* b2s  = (float*)(smem_raw + SM_B2);
    float* g2s  = (float*)(smem_raw + SM_G2);
    float* be2s = (float*)(smem_raw + SM_BE2);
    float* w3s  = (float*)(smem_raw + SM_W3);

    const int tid = threadIdx.x;
    const int wid = tid >> 5, lane = tid & 31;
    const int e0 = blockIdx.x * BM;
    const int r0 = wid * 16;

    // Batched index load FIRST; latency hidden behind smem fill + barrier.
    int eidx = e0 + r0 + (lane & 15);
    if (eidx >= E) eidx = E - 1;
    const int idx32 = (lane < 16) ? src[eidx] : dst[eidx];

    if (tid < 64) {
        g1h[tid]  = __floats2half2_rn(g1[2 * tid],  g1[2 * tid + 1]);
        be1h[tid] = __floats2half2_rn(be1[2 * tid], be1[2 * tid + 1]);
    }
    if (tid < HID2) { b2s[tid] = b2[tid]; g2s[tid] = g2[tid]; be2s[tid] = be2[tid]; w3s[tid] = W3[tid]; }

    {
        const uint4* __restrict__ w2v = (const uint4*)g_W2p;
        #pragma unroll
        for (int i = tid; i < 1024; i += THREADS)
            ((uint4*)Bp)[i] = w2v[i];
    }
    __syncthreads();

    // ---------------- Phase 1: warp-local rows, half2 LN+GELU --------------
    {
        const __half2 gA = g1h[lane * 2],  gB = g1h[lane * 2 + 1];
        const __half2 eA = be1h[lane * 2], eB = be1h[lane * 2 + 1];

        uint2 ap[2][4], qp[2][4];
        float sv[2][4];
        #pragma unroll
        for (int r = 0; r < 4; ++r) {
            const int s = __shfl_sync(0xffffffffu, idx32, r);
            const int d = __shfl_sync(0xffffffffu, idx32, 16 + r);
            ap[0][r] = *(const uint2*)(g_PdrugH + (size_t)s * HID + lane * 4);
            qp[0][r] = *(const uint2*)(g_PdisH  + (size_t)d * HID + lane * 4);
            sv[0][r] = g_Sdrug[s] + g_Sdis[d];
        }

        #pragma unroll
        for (int ib = 0; ib < 4; ++ib) {
            const int cur = ib & 1, nxt = cur ^ 1;
            if (ib < 3) {
                #pragma unroll
                for (int r = 0; r < 4; ++r) {
                    const int s = __shfl_sync(0xffffffffu, idx32, (ib + 1) * 4 + r);
                    const int d = __shfl_sync(0xffffffffu, idx32, 16 + (ib + 1) * 4 + r);
                    ap[nxt][r] = *(const uint2*)(g_PdrugH + (size_t)s * HID + lane * 4);
                    qp[nxt][r] = *(const uint2*)(g_PdisH  + (size_t)d * HID + lane * 4);
                    sv[nxt][r] = g_Sdrug[s] + g_Sdis[d];
                }
            }
            #pragma unroll
            for (int r = 0; r < 4; ++r) {
                const __half2 v0 = __hadd2(*(const __half2*)&ap[cur][r].x,
                                           *(const __half2*)&qp[cur][r].x);
                const __half2 v1 = __hadd2(*(const __half2*)&ap[cur][r].y,
                                           *(const __half2*)&qp[cur][r].y);
                const float2 f0 = __half22float2(v0);
                const float2 f1 = __half22float2(v1);
                float s2r = f0.x*f0.x + f0.y*f0.y + f1.x*f1.x + f1.y*f1.y;
                #pragma unroll
                for (int m = 16; m > 0; m >>= 1)
                    s2r += __shfl_xor_sync(0xffffffffu, s2r, m);
                const float mu = sv[cur][r] * (1.0f / HID);
                const float var = s2r * (1.0f / HID) - mu * mu;
                const float rs  = rsqrtf(var + 1e-5f);
                const __half2 mu2 = __float2half2_rn(mu);
                const __half2 rs2 = __float2half2_rn(rs);
                const __half2 z0 = __hfma2(__hmul2(__hsub2(v0, mu2), rs2), gA, eA);
                const __half2 z1 = __hfma2(__hmul2(__hsub2(v1, mu2), rs2), gB, eB);
                const __half2 h0 = gelu2h(z0);
                const __half2 h1 = gelu2h(z1);
                uint2 pk;
                pk.x = *(const uint32_t*)&h0;
                pk.y = *(const uint32_t*)&h1;
                *(uint2*)(As + (r0 + ib * 4 + r) * APITCH + lane * 4) = pk;
            }
        }
    }
    __syncwarp();   // A rows are warp-private

    // ---------------- Phase 2: HMMA m16n8k16; A scalar LDS, B LDS.64 -------
    const int gid = lane >> 2, tig = lane & 3;

    float acc[8][4];
    #pragma unroll
    for (int nt = 0; nt < 8; ++nt)
        #pragma unroll
        for (int j = 0; j < 4; ++j) acc[nt][j] = 0.0f;

    #pragma unroll
    for (int kt = 0; kt < 8; ++kt) {
        const int k0 = kt * 16;
        const uint32_t* arow0 = (const uint32_t*)(As + (r0 + gid) * APITCH + k0);
        const uint32_t* arow8 = (const uint32_t*)(As + (r0 + gid + 8) * APITCH + k0);
        uint32_t a0 = arow0[tig];
        uint32_t a1 = arow8[tig];
        uint32_t a2 = arow0[tig + 4];
        uint32_t a3 = arow8[tig + 4];
        #pragma unroll
        for (int nt = 0; nt < 8; ++nt) {
            const uint2 bw = Bp[(nt * 8 + kt) * 32 + lane];
            asm volatile(
                "mma.sync.aligned.m16n8k16.row.col.f32.f16.f16.f32 "
                "{%0,%1,%2,%3}, {%4,%5,%6,%7}, {%8,%9}, {%0,%1,%2,%3};"
                : "+f"(acc[nt][0]), "+f"(acc[nt][1]), "+f"(acc[nt][2]), "+f"(acc[nt][3])
                : "r"(a0), "r"(a1), "r"(a2), "r"(a3), "r"(bw.x), "r"(bw.y));
        }
    }

    // ---------------- Phase 3: +b2 (in acc) ; LN(64) ; GELU ; dot(W3)+b3 ---
    float s1a = 0.f, s2a = 0.f, s1b = 0.f, s2b = 0.f;
    #pragma unroll
    for (int nt = 0; nt < 8; ++nt) {
        #pragma unroll
        for (int j = 0; j < 2; ++j) {
            const float bb = b2s[nt * 8 + 2 * tig + j];
            acc[nt][j]     += bb;
            acc[nt][2 + j] += bb;
            const float tA = acc[nt][j];
            const float tB = acc[nt][2 + j];
            s1a += tA; s2a += tA * tA;
            s1b += tB; s2b += tB * tB;
        }
    }
    #pragma unroll
    for (int m = 1; m <= 2; m <<= 1) {
        s1a += __shfl_xor_sync(0xffffffffu, s1a, m);
        s2a += __shfl_xor_sync(0xffffffffu, s2a, m);
        s1b += __shfl_xor_sync(0xffffffffu, s1b, m);
        s2b += __shfl_xor_sync(0xffffffffu, s2b, m);
    }
    const float muA = s1a * (1.0f / HID2);
    const float rsA = rsqrtf(s2a * (1.0f / HID2) - muA * muA + 1e-5f);
    const float muB = s1b * (1.0f / HID2);
    const float rsB = rsqrtf(s2b * (1.0f / HID2) - muB * muB + 1e-5f);

    float dotA = 0.f, dotB = 0.f;
    #pragma unroll
    for (int nt = 0; nt < 8; ++nt) {
        #pragma unroll
        for (int j = 0; j < 2; ++j) {
            const int col = nt * 8 + 2 * tig + j;
            const float gg = g2s[col], be = be2s[col], ww = w3s[col];
            dotA = fmaf(gelu_fast((acc[nt][j]     - muA) * rsA * gg + be), ww, dotA);
            dotB = fmaf(gelu_fast((acc[nt][2 + j] - muB) * rsB * gg + be), ww, dotB);
        }
    }
    #pragma unroll
    for (int m = 1; m <= 2; m <<= 1) {
        dotA += __shfl_xor_sync(0xffffffffu, dotA, m);
        dotB += __shfl_xor_sync(0xffffffffu, dotB, m);
    }

    if (tig == 0) {
        const float b3v = b3[0];
        const int eA = e0 + r0 + gid;
        const int eB = eA + 8;
        if (eA < E) out[eA] = dotA + b3v;
        if (eB < E) out[eB] = dotB + b3v;
    }
}

// ---------------------------------------------------------------------------
extern "C" void kernel_launch(void* const* d_in, const int* in_sizes, int n_in,
                              void* d_out, int out_size)
{
    const float* drug = (const float*)d_in[0];
    const float* dis  = (const float*)d_in[1];
    const int*   src  = (const int*)  d_in[2];
    const int*   dst  = (const int*)  d_in[3];
    const float* W1   = (const float*)d_in[4];
    const float* b1   = (const float*)d_in[5];
    const float* g1   = (const float*)d_in[6];
    const float* be1  = (const float*)d_in[7];
    const float* W2   = (const float*)d_in[8];
    const float* b2   = (const float*)d_in[9];
    const float* g2   = (const float*)d_in[10];
    const float* be2  = (const float*)d_in[11];
    const float* W3   = (const float*)d_in[12];
    const float* b3   = (const float*)d_in[13];
    float* out = (float*)d_out;

    const int n_drug = in_sizes[0] / FEAT;
    const int n_dis  = in_sizes[1] / FEAT;
    const int E      = in_sizes[2];

    const int nmax = n_drug > n_dis ? n_drug : n_dis;
    dim3 pgrid((nmax + 31) / 32 + 1, 2);
    precompute_kernel<<<pgrid, THREADS>>>(drug, dis, W1, b1, W2, n_drug, n_dis);

    cudaFuncSetAttribute(edge_kernel, cudaFuncAttributeMaxDynamicSharedMemorySize, SM_TOTAL);
    const int blocks = (E + BM - 1) / BM;
    edge_kernel<<<blocks, THREADS, SM_TOTAL>>>(
        src, dst, g1, be1, b2, g2, be2, W3, b3, out, E);
}